// round 15
// baseline (speedup 1.0000x reference)
#include <cuda_runtime.h>

#define D      128
#define NMAX   50000
#define EMAX   800000
#define GIN_EPS 0.1f
#define SPAD   132   // padded smem row stride (words) -> conflict-free MMA A-loads
#define DEGMAX 72    // bucket slots per node (Poisson(16): P(deg>72) ~ 1e-16)

// ---------------- device-resident configuration ----------------
struct Cfg {
    unsigned long long x;      // node features
    unsigned long long ei;     // edge_index
    unsigned long long ew;     // edge_weight
    unsigned long long w[4];   // W1a, W1b, W2a, W2b
    int E;
    int is64;
};
__device__ Cfg g_cfg;

__device__ int g_deg[NMAX];
__device__ __align__(16) float2 g_adj[(size_t)NMAX * DEGMAX];  // {src_bits, weight}
__device__ __align__(16) float  g_bufB[(size_t)NMAX * D];      // h after layer 1
// B fragments packed as uint4 tile-PAIRS: per weight, 128 pairs (kt*8+tp) x 32 lanes
// entry = { frag(kt, 2tp).x, frag(kt, 2tp).y, frag(kt, 2tp+1).x, frag(kt, 2tp+1).y }
__device__ __align__(16) uint4  g_wpk[4 * 4096];

struct KArgs {
    unsigned long long p[12];
    long long          sz[12];
    int n_in;
    int N;
};

__device__ __forceinline__ unsigned f2tf(float f) {
    unsigned u;
    asm("cvt.rna.tf32.f32 %0, %1;" : "=r"(u) : "f"(f));
    return u;
}

// ---------------- config kernel: classify inputs BY CONTENT (parallel scoring) ----------------
__global__ void k_config(KArgs a) {
    __shared__ int gs[12];   // "gaussian-like" score
    __shared__ int us[12];   // "[0,1]-like" score
    __shared__ int hz[12];   // 1 if all sampled odd int32 words are zero (int64 signature)
    const int tid = threadIdx.x;

    if (tid < 12) { gs[tid] = 0; us[tid] = 0; hz[tid] = 1; }
    __syncthreads();

    for (int i = 0; i < a.n_in; i++) {
        long long s = a.sz[i];
        if (s <= 0) continue;
        const float* f = (const float*)a.p[i];
        long long idx = (long long)tid * (s - 1) / 255;
        float v = f[idx];
        bool fin = isfinite(v);
        if (fin && fabsf(v) > 1e-6f && fabsf(v) < 1e4f) atomicAdd(&gs[i], 1);
        if (fin && v >= 0.0f && v <= 1.0f)              atomicAdd(&us[i], 1);
        const int* w32 = (const int*)a.p[i];
        long long pairs = s / 2; if (pairs > 256) pairs = 256;
        if (tid < pairs && w32[2 * tid + 1] != 0) hz[i] = 0;
    }
    __syncthreads();

    if (tid != 0) return;

    Cfg c;
    bool used[12];
    for (int i = 0; i < 12; i++) used[i] = (i >= a.n_in);

    int nw = 0;
    for (int i = 0; i < a.n_in; i++)
        if (!used[i] && a.sz[i] == 16384 && nw < 4) { c.w[nw++] = a.p[i]; used[i] = true; }
    while (nw < 4) c.w[nw++] = a.p[0];

    long long xneed = (long long)a.N * 128;
    int xi = -1, best = -1;
    for (int i = 0; i < a.n_in; i++)
        if (!used[i] && a.sz[i] == xneed && gs[i] > best) { best = gs[i]; xi = i; }
    if (xi < 0) {
        long long b = -1;
        for (int i = 0; i < a.n_in; i++)
            if (!used[i] && a.sz[i] > b) { b = a.sz[i]; xi = i; }
        if (xi < 0) xi = 0;
    }
    c.x = a.p[xi]; used[xi] = true;

    int ewi = -1; best = -1;
    for (int i = 0; i < a.n_in; i++) {
        if (used[i]) continue;
        long long s = a.sz[i];
        if (s < 1 || s > EMAX) continue;
        if (us[i] > best) { best = us[i]; ewi = i; }
    }
    if (ewi < 0) {
        long long b = (long long)1 << 62;
        for (int i = 0; i < a.n_in; i++)
            if (!used[i] && a.sz[i] < b) { b = a.sz[i]; ewi = i; }
        if (ewi < 0) ewi = 0;
    }
    c.ew = a.p[ewi]; used[ewi] = true;
    long long Ell = a.sz[ewi];
    c.E = (int)(Ell > EMAX ? EMAX : Ell);

    int eii = -1; long long b2 = -1;
    for (int i = 0; i < a.n_in; i++)
        if (!used[i] && a.sz[i] > b2) { b2 = a.sz[i]; eii = i; }
    if (eii < 0) eii = ewi;
    c.ei = a.p[eii];
    c.is64 = hz[eii];

    g_cfg = c;
}

// ---------------- prep: pack weights to tf32 B-fragment tile-pairs + zero degree ----------------
__global__ void k_prep(int n) {
    int i = blockIdx.x * blockDim.x + threadIdx.x;
    if (i < 4096) {                    // 128 tile-pairs x 32 lanes per weight
        int tp_idx = i >> 5;           // 0..127
        int lane   = i & 31;
        int kt     = tp_idx >> 3;      // 0..15
        int tp     = tp_idx & 7;       // 0..7  (n-tiles 2tp, 2tp+1)
        int gid    = lane >> 2;
        int tig    = lane & 3;
        int k      = kt * 8 + tig;
        int n0     = (2 * tp) * 8 + gid;
        int n1     = (2 * tp + 1) * 8 + gid;
        #pragma unroll
        for (int w = 0; w < 4; w++) {
            const float* W = (const float*)g_cfg.w[w];
            uint4 b;
            b.x = f2tf(W[k * 128 + n0]);
            b.y = f2tf(W[(k + 4) * 128 + n0]);
            b.z = f2tf(W[k * 128 + n1]);
            b.w = f2tf(W[(k + 4) * 128 + n1]);
            g_wpk[w * 4096 + i] = b;
        }
    }
    if (i < n) g_deg[i] = 0;
}

// ---------------- helpers ----------------
__device__ __forceinline__ int load_idx(size_t pos) {
    if (g_cfg.is64) return (int)((const long long*)g_cfg.ei)[pos];
    return ((const int*)g_cfg.ei)[pos];
}

__global__ void k_zero_out(float* out, long long n) {
    long long i = (long long)blockIdx.x * blockDim.x + threadIdx.x;
    if (i < n) out[i] = 0.0f;
}

// ---------------- one-pass bucket build (4 edges/thread, batched loads) ----------------
__global__ void k_build(int n) {
    int base = (blockIdx.x * blockDim.x + threadIdx.x) * 4;
    int E = g_cfg.E;
    if (base >= E) return;

    int   d[4], s[4];
    float w[4];
    bool  ok[4];
    #pragma unroll
    for (int j = 0; j < 4; j++) {
        int e = base + j;
        ok[j] = (e < E);
        if (ok[j]) {
            d[j] = load_idx((size_t)E + e);
            s[j] = load_idx(e);
            w[j] = ((const float*)g_cfg.ew)[e];
            ok[j] = (unsigned)d[j] < (unsigned)n && (unsigned)s[j] < (unsigned)n;
        }
    }
    #pragma unroll
    for (int j = 0; j < 4; j++) {
        if (ok[j]) {
            int slot = atomicAdd(&g_deg[d[j]], 1);
            if (slot < DEGMAX) {
                float2 ent;
                ent.x = __int_as_float(s[j]);
                ent.y = w[j];
                g_adj[(size_t)d[j] * DEGMAX + slot] = ent;
            }
        }
    }
}

// ---------------- fused GIN layer: gather + 2-layer tf32 MMA MLP ----------------
__device__ __forceinline__ void mma_tf32(float& c0, float& c1, float& c2, float& c3,
                                         unsigned a0, unsigned a1, unsigned a2, unsigned a3,
                                         unsigned b0, unsigned b1) {
    asm volatile(
        "mma.sync.aligned.m16n8k8.row.col.f32.tf32.tf32.f32 "
        "{%0,%1,%2,%3}, {%4,%5,%6,%7}, {%8,%9}, {%0,%1,%2,%3};"
        : "+f"(c0), "+f"(c1), "+f"(c2), "+f"(c3)
        : "r"(a0), "r"(a1), "r"(a2), "r"(a3), "r"(b0), "r"(b1));
}

template <int LAYER>
__global__ void __launch_bounds__(256) k_gin(float* __restrict__ OutExt, int n) {
    __shared__ __align__(16) unsigned sZ[32 * SPAD];   // tf32 bits, padded rows
    __shared__ __align__(16) unsigned sT[32 * SPAD];

    const uint4* Wa = g_wpk + (LAYER == 1 ? 0 : 2) * 4096;
    const uint4* Wb = g_wpk + (LAYER == 1 ? 1 : 3) * 4096;

    const int tid  = threadIdx.x;
    const int wid  = tid >> 5;
    const int lane = tid & 31;
    const int row0 = blockIdx.x * 32;

    const float* h = (LAYER == 1) ? (const float*)g_cfg.x : g_bufB;

    // ---- phase A: gather 4 nodes per warp ----
    #pragma unroll
    for (int j = 0; j < 4; j++) {
        int r    = wid * 4 + j;       // 0..31
        int node = row0 + r;
        float4 acc = make_float4(0.f, 0.f, 0.f, 0.f);
        if (node < n) {
            acc = ((const float4*)(h + (size_t)node * D))[lane];
            acc.x *= (1.0f + GIN_EPS);
            acc.y *= (1.0f + GIN_EPS);
            acc.z *= (1.0f + GIN_EPS);
            acc.w *= (1.0f + GIN_EPS);

            int deg = g_deg[node];
            if (deg > DEGMAX) deg = DEGMAX;
            const float2* adj  = g_adj + (size_t)node * DEGMAX;
            const float4* adj4 = (const float4*)adj;   // 2 edges per entry (rows 16B-aligned)

            int k = 0;
            for (; k + 4 <= deg; k += 4) {
                float4 p0 = adj4[(k >> 1)];        // edges k, k+1
                float4 p1 = adj4[(k >> 1) + 1];    // edges k+2, k+3
                float4 v0 = ((const float4*)(h + (size_t)__float_as_int(p0.x) * D))[lane];
                float4 v1 = ((const float4*)(h + (size_t)__float_as_int(p0.z) * D))[lane];
                float4 v2 = ((const float4*)(h + (size_t)__float_as_int(p1.x) * D))[lane];
                float4 v3 = ((const float4*)(h + (size_t)__float_as_int(p1.z) * D))[lane];
                acc.x = fmaf(p0.y, v0.x, fmaf(p0.w, v1.x, fmaf(p1.y, v2.x, fmaf(p1.w, v3.x, acc.x))));
                acc.y = fmaf(p0.y, v0.y, fmaf(p0.w, v1.y, fmaf(p1.y, v2.y, fmaf(p1.w, v3.y, acc.y))));
                acc.z = fmaf(p0.y, v0.z, fmaf(p0.w, v1.z, fmaf(p1.y, v2.z, fmaf(p1.w, v3.z, acc.z))));
                acc.w = fmaf(p0.y, v0.w, fmaf(p0.w, v1.w, fmaf(p1.y, v2.w, fmaf(p1.w, v3.w, acc.w))));
            }
            for (; k < deg; k++) {
                float2 e = adj[k];
                float4 v = ((const float4*)(h + (size_t)__float_as_int(e.x) * D))[lane];
                acc.x = fmaf(e.y, v.x, acc.x);
                acc.y = fmaf(e.y, v.y, acc.y);
                acc.z = fmaf(e.y, v.z, acc.z);
                acc.w = fmaf(e.y, v.w, acc.w);
            }
        }
        uint4 u;
        u.x = f2tf(acc.x); u.y = f2tf(acc.y); u.z = f2tf(acc.z); u.w = f2tf(acc.w);
        *(uint4*)(sZ + r * SPAD + lane * 4) = u;
    }
    __syncthreads();

    // ---- phase B: MMA ----
    const int gid  = lane >> 2;
    const int tig  = lane & 3;
    const int mrow = (wid >> 2) * 16;   // 0 or 16
    const int ncol = (wid & 3) * 32;    // 0,32,64,96
    const int tp0  = ncol >> 4;         // first tile-pair (0,2,4,6)

    float c[4][4];
    #pragma unroll
    for (int t = 0; t < 4; t++)
        #pragma unroll
        for (int jj = 0; jj < 4; jj++) c[t][jj] = 0.f;

    // stage 1: T = relu(Z @ Wa)
    #pragma unroll
    for (int k0 = 0; k0 < 128; k0 += 8) {
        const unsigned* zr = sZ + k0 + tig;
        unsigned a0 = zr[(mrow + gid)     * SPAD];
        unsigned a1 = zr[(mrow + gid + 8) * SPAD];
        unsigned a2 = zr[(mrow + gid)     * SPAD + 4];
        unsigned a3 = zr[(mrow + gid + 8) * SPAD + 4];
        const uint4* wt = Wa + ((k0 >> 3) * 8 + tp0) * 32 + lane;
        #pragma unroll
        for (int p = 0; p < 2; p++) {
            uint4 b = __ldg(wt + p * 32);
            mma_tf32(c[2*p][0],   c[2*p][1],   c[2*p][2],   c[2*p][3],   a0, a1, a2, a3, b.x, b.y);
            mma_tf32(c[2*p+1][0], c[2*p+1][1], c[2*p+1][2], c[2*p+1][3], a0, a1, a2, a3, b.z, b.w);
        }
    }
    #pragma unroll
    for (int t = 0; t < 4; t++) {
        int n0 = ncol + t * 8 + 2 * tig;
        sT[(mrow + gid)     * SPAD + n0]     = f2tf(fmaxf(c[t][0], 0.f));
        sT[(mrow + gid)     * SPAD + n0 + 1] = f2tf(fmaxf(c[t][1], 0.f));
        sT[(mrow + gid + 8) * SPAD + n0]     = f2tf(fmaxf(c[t][2], 0.f));
        sT[(mrow + gid + 8) * SPAD + n0 + 1] = f2tf(fmaxf(c[t][3], 0.f));
        c[t][0] = c[t][1] = c[t][2] = c[t][3] = 0.f;
    }
    __syncthreads();

    // stage 2: Out = act2(T @ Wb)
    #pragma unroll
    for (int k0 = 0; k0 < 128; k0 += 8) {
        const unsigned* tr = sT + k0 + tig;
        unsigned a0 = tr[(mrow + gid)     * SPAD];
        unsigned a1 = tr[(mrow + gid + 8) * SPAD];
        unsigned a2 = tr[(mrow + gid)     * SPAD + 4];
        unsigned a3 = tr[(mrow + gid + 8) * SPAD + 4];
        const uint4* wt = Wb + ((k0 >> 3) * 8 + tp0) * 32 + lane;
        #pragma unroll
        for (int p = 0; p < 2; p++) {
            uint4 b = __ldg(wt + p * 32);
            mma_tf32(c[2*p][0],   c[2*p][1],   c[2*p][2],   c[2*p][3],   a0, a1, a2, a3, b.x, b.y);
            mma_tf32(c[2*p+1][0], c[2*p+1][1], c[2*p+1][2], c[2*p+1][3], a0, a1, a2, a3, b.z, b.w);
        }
    }

    float* Out = (LAYER == 1) ? g_bufB : OutExt;
    int r0 = row0 + mrow + gid;
    int r1 = r0 + 8;
    #pragma unroll
    for (int t = 0; t < 4; t++) {
        int n0 = ncol + t * 8 + 2 * tig;
        float v0 = c[t][0], v1 = c[t][1], v2 = c[t][2], v3 = c[t][3];
        if (LAYER == 1) {
            v0 = fmaxf(v0, 0.f); v1 = fmaxf(v1, 0.f);
            v2 = fmaxf(v2, 0.f); v3 = fmaxf(v3, 0.f);
        }
        if (r0 < n) {
            Out[(size_t)r0 * D + n0]     = v0;
            Out[(size_t)r0 * D + n0 + 1] = v1;
        }
        if (r1 < n) {
            Out[(size_t)r1 * D + n0]     = v2;
            Out[(size_t)r1 * D + n0 + 1] = v3;
        }
    }
}

// ---------------- launch ----------------
extern "C" void kernel_launch(void* const* d_in, const int* in_sizes, int n_in,
                              void* d_out, int out_size) {
    float* out = (float*)d_out;

    int N = out_size / D;
    if (N > NMAX) N = NMAX;
    if (N < 1)    N = 1;

    KArgs a;
    int m = n_in < 12 ? n_in : 12;
    for (int i = 0; i < 12; i++) { a.p[i] = 0; a.sz[i] = 0; }
    for (int i = 0; i < m; i++) {
        a.p[i]  = (unsigned long long)d_in[i];
        a.sz[i] = in_sizes[i];
    }
    a.n_in = m;
    a.N    = N;

    long long Eest = 0;
    for (int i = 0; i < m; i++) {
        long long s = in_sizes[i];
        if (s == 16384 || s == (long long)N * D) continue;
        if (s <= EMAX && s > Eest) Eest = s;
    }
    if (Eest <= 0) Eest = EMAX;

    const int edgeGrid = (int)((Eest + 1023) / 1024);   // 4 edges per thread
    const int ginGrid  = (N + 31) / 32;
    const int prepN    = (N > 4096 ? N : 4096);

    k_config<<<1, 256>>>(a);
    k_prep<<<(prepN + 255) / 256, 256>>>(N);
    if ((long long)N * D != (long long)out_size)
        k_zero_out<<<(int)((out_size + 255) / 256), 256>>>(out, (long long)out_size);

    // one-pass bucket adjacency
    k_build<<<edgeGrid, 256>>>(N);

    // fused layers
    k_gin<1><<<ginGrid, 256>>>(out, N);
    k_gin<2><<<ginGrid, 256>>>(out, N);
}

// round 16
// speedup vs baseline: 1.0535x; 1.0535x over previous
#include <cuda_runtime.h>

#define D      128
#define NMAX   50000
#define EMAX   800000
#define GIN_EPS 0.1f
#define SPAD   132   // padded smem row stride (words) -> conflict-free MMA A-loads
#define DEGMAX 72    // bucket slots per node (Poisson(16): P(deg>72) ~ 1e-16)

// ---------------- device-resident configuration ----------------
struct Cfg {
    unsigned long long x;      // node features
    unsigned long long ei;     // edge_index
    unsigned long long ew;     // edge_weight
    unsigned long long w[4];   // W1a, W1b, W2a, W2b
    int E;
    int is64;
};
__device__ Cfg g_cfg;

__device__ int g_deg[NMAX];
__device__ __align__(16) float2 g_adj[(size_t)NMAX * DEGMAX];  // {src_bits, weight}
__device__ __align__(16) float  g_bufB[(size_t)NMAX * D];      // h after layer 1
// B fragments packed in mma order: per weight, 256 tiles (kt*16+nt) x 32 lanes x uint2
__device__ __align__(16) uint2  g_wpk[4 * 8192];

struct KArgs {
    unsigned long long p[12];
    long long          sz[12];
    int n_in;
    int N;
};

__device__ __forceinline__ unsigned f2tf(float f) {
    unsigned u;
    asm("cvt.rna.tf32.f32 %0, %1;" : "=r"(u) : "f"(f));
    return u;
}

// ---------------- config kernel: classify inputs BY CONTENT (parallel scoring) ----------------
__global__ void k_config(KArgs a) {
    __shared__ int gs[12];   // "gaussian-like" score
    __shared__ int us[12];   // "[0,1]-like" score
    __shared__ int hz[12];   // 1 if all sampled odd int32 words are zero (int64 signature)
    const int tid = threadIdx.x;

    if (tid < 12) { gs[tid] = 0; us[tid] = 0; hz[tid] = 1; }
    __syncthreads();

    for (int i = 0; i < a.n_in; i++) {
        long long s = a.sz[i];
        if (s <= 0) continue;
        const float* f = (const float*)a.p[i];
        long long idx = (long long)tid * (s - 1) / 255;
        float v = f[idx];
        bool fin = isfinite(v);
        if (fin && fabsf(v) > 1e-6f && fabsf(v) < 1e4f) atomicAdd(&gs[i], 1);
        if (fin && v >= 0.0f && v <= 1.0f)              atomicAdd(&us[i], 1);
        const int* w32 = (const int*)a.p[i];
        long long pairs = s / 2; if (pairs > 256) pairs = 256;
        if (tid < pairs && w32[2 * tid + 1] != 0) hz[i] = 0;
    }
    __syncthreads();

    if (tid != 0) return;

    Cfg c;
    bool used[12];
    for (int i = 0; i < 12; i++) used[i] = (i >= a.n_in);

    int nw = 0;
    for (int i = 0; i < a.n_in; i++)
        if (!used[i] && a.sz[i] == 16384 && nw < 4) { c.w[nw++] = a.p[i]; used[i] = true; }
    while (nw < 4) c.w[nw++] = a.p[0];

    long long xneed = (long long)a.N * 128;
    int xi = -1, best = -1;
    for (int i = 0; i < a.n_in; i++)
        if (!used[i] && a.sz[i] == xneed && gs[i] > best) { best = gs[i]; xi = i; }
    if (xi < 0) {
        long long b = -1;
        for (int i = 0; i < a.n_in; i++)
            if (!used[i] && a.sz[i] > b) { b = a.sz[i]; xi = i; }
        if (xi < 0) xi = 0;
    }
    c.x = a.p[xi]; used[xi] = true;

    int ewi = -1; best = -1;
    for (int i = 0; i < a.n_in; i++) {
        if (used[i]) continue;
        long long s = a.sz[i];
        if (s < 1 || s > EMAX) continue;
        if (us[i] > best) { best = us[i]; ewi = i; }
    }
    if (ewi < 0) {
        long long b = (long long)1 << 62;
        for (int i = 0; i < a.n_in; i++)
            if (!used[i] && a.sz[i] < b) { b = a.sz[i]; ewi = i; }
        if (ewi < 0) ewi = 0;
    }
    c.ew = a.p[ewi]; used[ewi] = true;
    long long Ell = a.sz[ewi];
    c.E = (int)(Ell > EMAX ? EMAX : Ell);

    int eii = -1; long long b2 = -1;
    for (int i = 0; i < a.n_in; i++)
        if (!used[i] && a.sz[i] > b2) { b2 = a.sz[i]; eii = i; }
    if (eii < 0) eii = ewi;
    c.ei = a.p[eii];
    c.is64 = hz[eii];

    g_cfg = c;
}

// ---------------- prep: pack weights to tf32 B-fragments + zero degree ----------------
__global__ void k_prep(int n) {
    int i = blockIdx.x * blockDim.x + threadIdx.x;
    if (i < 8192) {
        int tile = i >> 5;
        int lane = i & 31;
        int kt   = tile >> 4;
        int nt   = tile & 15;
        int gid  = lane >> 2;
        int tig  = lane & 3;
        int k    = kt * 8 + tig;
        int nn   = nt * 8 + gid;
        #pragma unroll
        for (int w = 0; w < 4; w++) {
            const float* W = (const float*)g_cfg.w[w];
            uint2 b;
            b.x = f2tf(W[k * 128 + nn]);
            b.y = f2tf(W[(k + 4) * 128 + nn]);
            g_wpk[w * 8192 + i] = b;
        }
    }
    if (i < n) g_deg[i] = 0;
}

// ---------------- helpers ----------------
__device__ __forceinline__ int load_idx(size_t pos) {
    if (g_cfg.is64) return (int)((const long long*)g_cfg.ei)[pos];
    return ((const int*)g_cfg.ei)[pos];
}

__global__ void k_zero_out(float* out, long long n) {
    long long i = (long long)blockIdx.x * blockDim.x + threadIdx.x;
    if (i < n) out[i] = 0.0f;
}

// ---------------- one-pass bucket build (4 edges/thread, batched loads) ----------------
__global__ void k_build(int n) {
    int base = (blockIdx.x * blockDim.x + threadIdx.x) * 4;
    int E = g_cfg.E;
    if (base >= E) return;

    int   d[4], s[4];
    float w[4];
    bool  ok[4];
    #pragma unroll
    for (int j = 0; j < 4; j++) {
        int e = base + j;
        ok[j] = (e < E);
        if (ok[j]) {
            d[j] = load_idx((size_t)E + e);
            s[j] = load_idx(e);
            w[j] = ((const float*)g_cfg.ew)[e];
            ok[j] = (unsigned)d[j] < (unsigned)n && (unsigned)s[j] < (unsigned)n;
        }
    }
    #pragma unroll
    for (int j = 0; j < 4; j++) {
        if (ok[j]) {
            int slot = atomicAdd(&g_deg[d[j]], 1);
            if (slot < DEGMAX) {
                float2 ent;
                ent.x = __int_as_float(s[j]);
                ent.y = w[j];
                g_adj[(size_t)d[j] * DEGMAX + slot] = ent;
            }
        }
    }
}

// ---------------- fused GIN layer: gather + 2-layer tf32 MMA MLP ----------------
__device__ __forceinline__ void mma_tf32(float& c0, float& c1, float& c2, float& c3,
                                         unsigned a0, unsigned a1, unsigned a2, unsigned a3,
                                         unsigned b0, unsigned b1) {
    asm volatile(
        "mma.sync.aligned.m16n8k8.row.col.f32.tf32.tf32.f32 "
        "{%0,%1,%2,%3}, {%4,%5,%6,%7}, {%8,%9}, {%0,%1,%2,%3};"
        : "+f"(c0), "+f"(c1), "+f"(c2), "+f"(c3)
        : "r"(a0), "r"(a1), "r"(a2), "r"(a3), "r"(b0), "r"(b1));
}

template <int LAYER>
__global__ void __launch_bounds__(256, 6) k_gin(float* __restrict__ OutExt, int n) {
    __shared__ __align__(16) unsigned sZ[32 * SPAD];   // tf32 bits, padded rows
    __shared__ __align__(16) unsigned sT[32 * SPAD];

    const uint2* Wa = g_wpk + (LAYER == 1 ? 0 : 2) * 8192;
    const uint2* Wb = g_wpk + (LAYER == 1 ? 1 : 3) * 8192;

    const int tid  = threadIdx.x;
    const int wid  = tid >> 5;
    const int lane = tid & 31;
    const int row0 = blockIdx.x * 32;

    const float* h = (LAYER == 1) ? (const float*)g_cfg.x : g_bufB;

    // ---- phase A: gather 4 nodes per warp ----
    #pragma unroll
    for (int j = 0; j < 4; j++) {
        int r    = wid * 4 + j;       // 0..31
        int node = row0 + r;
        float4 acc = make_float4(0.f, 0.f, 0.f, 0.f);
        if (node < n) {
            acc = ((const float4*)(h + (size_t)node * D))[lane];
            acc.x *= (1.0f + GIN_EPS);
            acc.y *= (1.0f + GIN_EPS);
            acc.z *= (1.0f + GIN_EPS);
            acc.w *= (1.0f + GIN_EPS);

            int deg = g_deg[node];
            if (deg > DEGMAX) deg = DEGMAX;
            const float2* adj = g_adj + (size_t)node * DEGMAX;

            int k = 0;
            for (; k + 4 <= deg; k += 4) {
                float2 e0 = adj[k],     e1 = adj[k + 1];
                float2 e2 = adj[k + 2], e3 = adj[k + 3];
                float4 v0 = ((const float4*)(h + (size_t)__float_as_int(e0.x) * D))[lane];
                float4 v1 = ((const float4*)(h + (size_t)__float_as_int(e1.x) * D))[lane];
                float4 v2 = ((const float4*)(h + (size_t)__float_as_int(e2.x) * D))[lane];
                float4 v3 = ((const float4*)(h + (size_t)__float_as_int(e3.x) * D))[lane];
                acc.x = fmaf(e0.y, v0.x, fmaf(e1.y, v1.x, fmaf(e2.y, v2.x, fmaf(e3.y, v3.x, acc.x))));
                acc.y = fmaf(e0.y, v0.y, fmaf(e1.y, v1.y, fmaf(e2.y, v2.y, fmaf(e3.y, v3.y, acc.y))));
                acc.z = fmaf(e0.y, v0.z, fmaf(e1.y, v1.z, fmaf(e2.y, v2.z, fmaf(e3.y, v3.z, acc.z))));
                acc.w = fmaf(e0.y, v0.w, fmaf(e1.y, v1.w, fmaf(e2.y, v2.w, fmaf(e3.y, v3.w, acc.w))));
            }
            for (; k < deg; k++) {
                float2 e = adj[k];
                float4 v = ((const float4*)(h + (size_t)__float_as_int(e.x) * D))[lane];
                acc.x = fmaf(e.y, v.x, acc.x);
                acc.y = fmaf(e.y, v.y, acc.y);
                acc.z = fmaf(e.y, v.z, acc.z);
                acc.w = fmaf(e.y, v.w, acc.w);
            }
        }
        uint4 u;
        u.x = f2tf(acc.x); u.y = f2tf(acc.y); u.z = f2tf(acc.z); u.w = f2tf(acc.w);
        *(uint4*)(sZ + r * SPAD + lane * 4) = u;
    }
    __syncthreads();

    // ---- phase B: MMA ----
    const int gid  = lane >> 2;
    const int tig  = lane & 3;
    const int mrow = (wid >> 2) * 16;   // 0 or 16
    const int ncol = (wid & 3) * 32;    // 0,32,64,96
    const int ntile0 = ncol >> 3;

    float c[4][4];
    #pragma unroll
    for (int t = 0; t < 4; t++)
        #pragma unroll
        for (int jj = 0; jj < 4; jj++) c[t][jj] = 0.f;

    // stage 1: T = relu(Z @ Wa)
    #pragma unroll
    for (int k0 = 0; k0 < 128; k0 += 8) {
        const unsigned* zr = sZ + k0 + tig;
        unsigned a0 = zr[(mrow + gid)     * SPAD];
        unsigned a1 = zr[(mrow + gid + 8) * SPAD];
        unsigned a2 = zr[(mrow + gid)     * SPAD + 4];
        unsigned a3 = zr[(mrow + gid + 8) * SPAD + 4];
        const uint2* wt = Wa + ((k0 >> 3) * 16 + ntile0) * 32 + lane;
        #pragma unroll
        for (int t = 0; t < 4; t++) {
            uint2 b = __ldg(wt + t * 32);
            mma_tf32(c[t][0], c[t][1], c[t][2], c[t][3], a0, a1, a2, a3, b.x, b.y);
        }
    }
    #pragma unroll
    for (int t = 0; t < 4; t++) {
        int n0 = ncol + t * 8 + 2 * tig;
        sT[(mrow + gid)     * SPAD + n0]     = f2tf(fmaxf(c[t][0], 0.f));
        sT[(mrow + gid)     * SPAD + n0 + 1] = f2tf(fmaxf(c[t][1], 0.f));
        sT[(mrow + gid + 8) * SPAD + n0]     = f2tf(fmaxf(c[t][2], 0.f));
        sT[(mrow + gid + 8) * SPAD + n0 + 1] = f2tf(fmaxf(c[t][3], 0.f));
        c[t][0] = c[t][1] = c[t][2] = c[t][3] = 0.f;
    }
    __syncthreads();

    // stage 2: Out = act2(T @ Wb)
    #pragma unroll
    for (int k0 = 0; k0 < 128; k0 += 8) {
        const unsigned* tr = sT + k0 + tig;
        unsigned a0 = tr[(mrow + gid)     * SPAD];
        unsigned a1 = tr[(mrow + gid + 8) * SPAD];
        unsigned a2 = tr[(mrow + gid)     * SPAD + 4];
        unsigned a3 = tr[(mrow + gid + 8) * SPAD + 4];
        const uint2* wt = Wb + ((k0 >> 3) * 16 + ntile0) * 32 + lane;
        #pragma unroll
        for (int t = 0; t < 4; t++) {
            uint2 b = __ldg(wt + t * 32);
            mma_tf32(c[t][0], c[t][1], c[t][2], c[t][3], a0, a1, a2, a3, b.x, b.y);
        }
    }

    float* Out = (LAYER == 1) ? g_bufB : OutExt;
    int r0 = row0 + mrow + gid;
    int r1 = r0 + 8;
    #pragma unroll
    for (int t = 0; t < 4; t++) {
        int n0 = ncol + t * 8 + 2 * tig;
        float v0 = c[t][0], v1 = c[t][1], v2 = c[t][2], v3 = c[t][3];
        if (LAYER == 1) {
            v0 = fmaxf(v0, 0.f); v1 = fmaxf(v1, 0.f);
            v2 = fmaxf(v2, 0.f); v3 = fmaxf(v3, 0.f);
        }
        if (r0 < n) {
            Out[(size_t)r0 * D + n0]     = v0;
            Out[(size_t)r0 * D + n0 + 1] = v1;
        }
        if (r1 < n) {
            Out[(size_t)r1 * D + n0]     = v2;
            Out[(size_t)r1 * D + n0 + 1] = v3;
        }
    }
}

// ---------------- launch ----------------
extern "C" void kernel_launch(void* const* d_in, const int* in_sizes, int n_in,
                              void* d_out, int out_size) {
    float* out = (float*)d_out;

    int N = out_size / D;
    if (N > NMAX) N = NMAX;
    if (N < 1)    N = 1;

    KArgs a;
    int m = n_in < 12 ? n_in : 12;
    for (int i = 0; i < 12; i++) { a.p[i] = 0; a.sz[i] = 0; }
    for (int i = 0; i < m; i++) {
        a.p[i]  = (unsigned long long)d_in[i];
        a.sz[i] = in_sizes[i];
    }
    a.n_in = m;
    a.N    = N;

    long long Eest = 0;
    for (int i = 0; i < m; i++) {
        long long s = in_sizes[i];
        if (s == 16384 || s == (long long)N * D) continue;
        if (s <= EMAX && s > Eest) Eest = s;
    }
    if (Eest <= 0) Eest = EMAX;

    const int edgeGrid = (int)((Eest + 1023) / 1024);   // 4 edges per thread
    const int ginGrid  = (N + 31) / 32;
    const int prepN    = (N > 8192 ? N : 8192);

    k_config<<<1, 256>>>(a);
    k_prep<<<(prepN + 255) / 256, 256>>>(N);
    if ((long long)N * D != (long long)out_size)
        k_zero_out<<<(int)((out_size + 255) / 256), 256>>>(out, (long long)out_size);

    // one-pass bucket adjacency
    k_build<<<edgeGrid, 256>>>(N);

    // fused layers
    k_gin<1><<<ginGrid, 256>>>(out, N);
    k_gin<2><<<ginGrid, 256>>>(out, N);
}